// round 15
// baseline (speedup 1.0000x reference)
#include <cuda_runtime.h>
#include <math_constants.h>

// SoftMinLayer: W = 79998 windows (len 500, step 250); 5 segments of 100;
// banded DTW (|i-j|<=1) over squared-L2 costs; out = mean(exp(-0.01*sqrt(d))).
//
// TWO windows per warp (16-lane halves) x TWO INDEPENDENT TASKS per warp
// (windows 4q..4q+3) for within-warp ILP, PLUS row-major cell order (cells
// (m,m-1),(m,m),(m,m+1) all reuse the same xv; S re-read from smem per cell,
// shared by both tasks) to eliminate carry registers -> ~84 regs -> 3 CTAs/SM.
// Width-16 fold tree + width-16 broadcasts + 3-carry banded DTW per task.

#define SEGC   5
#define TPB    256
#define NW     8          // warps per block
#define BLOCKS 444        // 3 * 148, persistent

typedef unsigned long long u64;

__device__ __forceinline__ u64 f2_fma(u64 a, u64 b, u64 c) {
    u64 d; asm("fma.rn.f32x2 %0, %1, %2, %3;" : "=l"(d) : "l"(a), "l"(b), "l"(c)); return d;
}
__device__ __forceinline__ u64 f2_add(u64 a, u64 b) {
    u64 d; asm("add.rn.f32x2 %0, %1, %2;" : "=l"(d) : "l"(a), "l"(b)); return d;
}
__device__ __forceinline__ float f2_hadd(u64 v) {
    float lo, hi; asm("mov.b64 {%0, %1}, %2;" : "=f"(lo), "=f"(hi) : "l"(v));
    return lo + hi;
}

__device__ __forceinline__ float foldstep(float A, float B, bool p, int o) {
    float v = p ? B : A;
    float u = p ? A : B;
    return v + __shfl_xor_sync(0xffffffffu, u, o);
}
// After the 4-level width-16 fold, cell n sits at lane (within each half):
#define SRCLANE16(n) ((((n) & 1) << 3) | ((((n) >> 1) & 1) << 2) | \
                      ((((n) >> 2) & 1) << 1) | (((n) >> 3) & 1))

// Fold + broadcast + 3-carry banded DTW for one 13-cell accumulator set.
__device__ __forceinline__ float band_tail(const u64* acc,
                                           bool p8, bool p4, bool p2, bool p1)
{
    float a0  = f2_hadd(acc[0]),  a1  = f2_hadd(acc[1]),  a2  = f2_hadd(acc[2]);
    float a3  = f2_hadd(acc[3]),  a4  = f2_hadd(acc[4]),  a5  = f2_hadd(acc[5]);
    float a6  = f2_hadd(acc[6]),  a7  = f2_hadd(acc[7]),  a8  = f2_hadd(acc[8]);
    float a9  = f2_hadd(acc[9]),  a10 = f2_hadd(acc[10]), a11 = f2_hadd(acc[11]);
    float a12 = f2_hadd(acc[12]);

    float q0 = foldstep(a0,  a1,  p8, 8);
    float q1 = foldstep(a2,  a3,  p8, 8);
    float q2 = foldstep(a4,  a5,  p8, 8);
    float q3 = foldstep(a6,  a7,  p8, 8);
    float q4 = foldstep(a8,  a9,  p8, 8);
    float q5 = foldstep(a10, a11, p8, 8);
    float q6 = foldstep(a12, 0.0f, p8, 8);

    float r0 = foldstep(q0, q1, p4, 4);
    float r1 = foldstep(q2, q3, p4, 4);
    float r2 = foldstep(q4, q5, p4, 4);
    float r3 = foldstep(q6, 0.0f, p4, 4);

    float t0 = foldstep(r0, r1, p2, 2);
    float t1 = foldstep(r2, r3, p2, 2);

    float fin = foldstep(t0, t1, p1, 1);

    float C13[13];
#pragma unroll
    for (int n = 0; n < 13; ++n)
        C13[n] = __shfl_sync(0xffffffffu, fin, SRCLANE16(n), 16);

    // 3-carry banded DTW (cells: (m,m)=3m, (m,m-1)=3m-1, (m,m+1)=3m+1)
    const float INF = CUDART_INF_F;
    float pB = INF;
    float pC = C13[0];            // D[0][0]
    float pD = C13[1] + pC;       // D[0][1]
#pragma unroll
    for (int m = 1; m < SEGC; ++m) {
        float j0 = C13[3 * m - 1] + fminf(pB, pC);            // D[m][m-1]
        float j1 = C13[3 * m]     + fminf(fminf(pD, j0), pC); // D[m][m]
        float j2 = (m < SEGC - 1) ? (C13[3 * m + 1] + fminf(j1, pD)) : INF;
        pB = j0; pC = j1; pD = j2;
    }
    return pC;                    // D[4][4]
}

__global__ void zero_kernel(float* out) { out[0] = 0.0f; }

__global__ __launch_bounds__(TPB, 3)
void softmin_kernel(const float* __restrict__ x, const float* __restrict__ S,
                    float* __restrict__ out, int W, float invW)
{
    __shared__ float ssf[SEGC * 128];   // -S, segments padded 100 -> 128 (zeros)
    __shared__ float sred[NW];

    const int t = threadIdx.x;
    for (int i = t; i < SEGC * 128; i += TPB) {
        int seg = i >> 7, off = i & 127;
        ssf[i] = (off < 100) ? -S[seg * 100 + off] : 0.0f;
    }
    __syncthreads();
    const u64* ss2 = reinterpret_cast<const u64*>(ssf);   // [seg*64 + idx]

    const int lane = t & 31, warp = t >> 5;
    const int h    = lane >> 4;        // which window of each pair
    const int sub  = lane & 15;        // lane within half
    const int gq   = blockIdx.x * NW + warp;
    const int TQ   = gridDim.x * NW;
    const int NQ   = (W + 3) >> 2;     // quads of windows

    const bool p8 = (lane & 8) != 0;
    const bool p4 = (lane & 4) != 0;
    const bool p2 = (lane & 2) != 0;
    const bool p1 = (lane & 1) != 0;

    float xsum = 0.0f;

    for (int q = gq; q < NQ; q += TQ) {
        const int wA = 4 * q + h;          // task A windows
        const int wB = 4 * q + 2 + h;      // task B windows
        const int wcA = (wA < W) ? wA : (W - 1);
        const int wcB = (wB < W) ? wB : (W - 1);
        const u64* xwA = reinterpret_cast<const u64*>(x) + (size_t)wcA * 125u;
        const u64* xwB = reinterpret_cast<const u64*>(x) + (size_t)wcB * 125u;

        u64 accA[13], accB[13];
#pragma unroll
        for (int c = 0; c < 13; ++c) { accA[c] = 0ull; accB[c] = 0ull; }

        // Row-major: x-row m feeds cells (m,m-1)=3m-1, (m,m)=3m, (m,m+1)=3m+1.
#pragma unroll
        for (int m = 0; m < SEGC; ++m) {
            u64 xvA[4], xvB[4];
#pragma unroll
            for (int k = 0; k < 4; ++k) {
                const int idx = sub + 16 * k;
                const bool ok = (idx < 50);
                xvA[k] = ok ? xwA[m * 50 + idx] : 0ull;
                xvB[k] = ok ? xwB[m * 50 + idx] : 0ull;
            }
            if (m > 0) {
#pragma unroll
                for (int k = 0; k < 4; ++k) {
                    const int idx = sub + 16 * k;
                    u64 sv = ss2[(m - 1) * 64 + idx];          // -s[m-1]
                    { u64 d = f2_add(xvA[k], sv); accA[3 * m - 1] = f2_fma(d, d, accA[3 * m - 1]); }
                    { u64 d = f2_add(xvB[k], sv); accB[3 * m - 1] = f2_fma(d, d, accB[3 * m - 1]); }
                }
            }
#pragma unroll
            for (int k = 0; k < 4; ++k) {
                const int idx = sub + 16 * k;
                u64 sv = ss2[m * 64 + idx];                    // -s[m]
                { u64 d = f2_add(xvA[k], sv); accA[3 * m] = f2_fma(d, d, accA[3 * m]); }
                { u64 d = f2_add(xvB[k], sv); accB[3 * m] = f2_fma(d, d, accB[3 * m]); }
            }
            if (m < SEGC - 1) {
#pragma unroll
                for (int k = 0; k < 4; ++k) {
                    const int idx = sub + 16 * k;
                    u64 sv = ss2[(m + 1) * 64 + idx];          // -s[m+1]
                    { u64 d = f2_add(xvA[k], sv); accA[3 * m + 1] = f2_fma(d, d, accA[3 * m + 1]); }
                    { u64 d = f2_add(xvB[k], sv); accB[3 * m + 1] = f2_fma(d, d, accB[3 * m + 1]); }
                }
            }
        }

        // Two independent tails — ptxas interleaves their shfl chains.
        float dA = band_tail(accA, p8, p4, p2, p1);
        float dB = band_tail(accB, p8, p4, p2, p1);

        float xiA = __expf(-0.01f * sqrtf(dA));
        float xiB = __expf(-0.01f * sqrtf(dB));
        if (wA < W) xsum += xiA;
        if (wB < W) xsum += xiB;
    }

    // epilogue: lane 0 of each half carries its half's sum
    float v = (sub == 0) ? xsum : 0.0f;
    v += __shfl_xor_sync(0xffffffffu, v, 16);
    v += __shfl_xor_sync(0xffffffffu, v, 8);
    v += __shfl_xor_sync(0xffffffffu, v, 4);
    v += __shfl_xor_sync(0xffffffffu, v, 2);
    v += __shfl_xor_sync(0xffffffffu, v, 1);
    if ((t & 31) == 0) sred[warp] = v;
    __syncthreads();
    if (t == 0) {
        float s = 0.0f;
#pragma unroll
        for (int i = 0; i < NW; ++i) s += sred[i];
        atomicAdd(out, s * invW);
    }
}

extern "C" void kernel_launch(void* const* d_in, const int* in_sizes, int n_in,
                              void* d_out, int out_size)
{
    const float* x = (const float*)d_in[0];
    const float* S = (const float*)d_in[1];
    float* out = (float*)d_out;

    const int Q    = in_sizes[0];
    const int L    = in_sizes[1];       // 500
    const int step = L / 2;             // 250
    const int W    = (Q - L + step - 1) / step;   // 79998
    const float invW = 1.0f / (float)W;

    zero_kernel<<<1, 1>>>(out);
    softmin_kernel<<<BLOCKS, TPB>>>(x, S, out, W, invW);
}

// round 16
// speedup vs baseline: 1.3127x; 1.3127x over previous
#include <cuda_runtime.h>
#include <math_constants.h>

// SoftMinLayer: W = 79998 windows (len 500, step 250); 5 segments of 100;
// banded DTW (|i-j|<=1) over squared-L2 costs; out = mean(exp(-0.01*sqrt(d))).
//
// TWO windows per warp (16-lane halves) x TWO INDEPENDENT TASKS per warp
// (windows 4q..4q+3). Main loop covers f2 idx 0..47 in 3 FULL slices
// (no predication); the remainder (idx 48,49 of all 13 band cells) is packed
// across cells into lanes: 2 full-width FMA groups per task + pair-sum +
// owner-lane merge, replacing the 12.5%-utilized 4th slice. Width-16 fold
// tree + broadcasts + 3-carry banded DTW per task.

#define SEGC   5
#define TPB    256
#define NW     8          // warps per block
#define BLOCKS 296        // 2 * 148, persistent
#define SSTR   65         // u64 stride of -S rows (bank-spread padding)

typedef unsigned long long u64;

__device__ __forceinline__ u64 f2_fma(u64 a, u64 b, u64 c) {
    u64 d; asm("fma.rn.f32x2 %0, %1, %2, %3;" : "=l"(d) : "l"(a), "l"(b), "l"(c)); return d;
}
__device__ __forceinline__ u64 f2_add(u64 a, u64 b) {
    u64 d; asm("add.rn.f32x2 %0, %1, %2;" : "=l"(d) : "l"(a), "l"(b)); return d;
}
__device__ __forceinline__ float f2_hadd(u64 v) {
    float lo, hi; asm("mov.b64 {%0, %1}, %2;" : "=f"(lo), "=f"(hi) : "l"(v));
    return lo + hi;
}

__device__ __forceinline__ float foldstep(float A, float B, bool p, int o) {
    float v = p ? B : A;
    float u = p ? A : B;
    return v + __shfl_xor_sync(0xffffffffu, u, o);
}
// After the 4-level width-16 fold, stream n sits at lane (within each half):
#define SRCLANE16(n) ((((n) & 1) << 3) | ((((n) >> 1) & 1) << 2) | \
                      ((((n) >> 2) & 1) << 1) | (((n) >> 3) & 1))

// Fold + remainder-merge + broadcast + 3-carry banded DTW for one task.
// rem1 holds cell (sub/2) remainder pair-sum (cells 0..7) at lanes 2c,2c+1;
// rem2 likewise for cells 8..12 at lanes 0..9.
__device__ __forceinline__ float band_tail(const u64* acc,
                                           bool p8, bool p4, bool p2, bool p1,
                                           float rem1, float rem2,
                                           int n_own, int src1, int src2)
{
    float a0  = f2_hadd(acc[0]),  a1  = f2_hadd(acc[1]),  a2  = f2_hadd(acc[2]);
    float a3  = f2_hadd(acc[3]),  a4  = f2_hadd(acc[4]),  a5  = f2_hadd(acc[5]);
    float a6  = f2_hadd(acc[6]),  a7  = f2_hadd(acc[7]),  a8  = f2_hadd(acc[8]);
    float a9  = f2_hadd(acc[9]),  a10 = f2_hadd(acc[10]), a11 = f2_hadd(acc[11]);
    float a12 = f2_hadd(acc[12]);

    float q0 = foldstep(a0,  a1,  p8, 8);
    float q1 = foldstep(a2,  a3,  p8, 8);
    float q2 = foldstep(a4,  a5,  p8, 8);
    float q3 = foldstep(a6,  a7,  p8, 8);
    float q4 = foldstep(a8,  a9,  p8, 8);
    float q5 = foldstep(a10, a11, p8, 8);
    float q6 = foldstep(a12, 0.0f, p8, 8);

    float r0 = foldstep(q0, q1, p4, 4);
    float r1 = foldstep(q2, q3, p4, 4);
    float r2 = foldstep(q4, q5, p4, 4);
    float r3 = foldstep(q6, 0.0f, p4, 4);

    float t0 = foldstep(r0, r1, p2, 2);
    float t1 = foldstep(r2, r3, p2, 2);

    float fin = foldstep(t0, t1, p1, 1);

    // merge remainder into owner-lane totals
    float g1 = __shfl_sync(0xffffffffu, rem1, src1, 16);
    float g2 = __shfl_sync(0xffffffffu, rem2, src2, 16);
    fin += (n_own < 8) ? g1 : ((n_own < 13) ? g2 : 0.0f);

    float C13[13];
#pragma unroll
    for (int n = 0; n < 13; ++n)
        C13[n] = __shfl_sync(0xffffffffu, fin, SRCLANE16(n), 16);

    // 3-carry banded DTW (cells: (m,m)=3m, (m,m-1)=3m-1, (m,m+1)=3m+1)
    const float INF = CUDART_INF_F;
    float pB = INF;
    float pC = C13[0];            // D[0][0]
    float pD = C13[1] + pC;       // D[0][1]
#pragma unroll
    for (int m = 1; m < SEGC; ++m) {
        float j0 = C13[3 * m - 1] + fminf(pB, pC);            // D[m][m-1]
        float j1 = C13[3 * m]     + fminf(fminf(pD, j0), pC); // D[m][m]
        float j2 = (m < SEGC - 1) ? (C13[3 * m + 1] + fminf(j1, pD)) : INF;
        pB = j0; pC = j1; pD = j2;
    }
    return pC;                    // D[4][4]
}

__global__ void zero_kernel(float* out) { out[0] = 0.0f; }

__global__ __launch_bounds__(TPB, 2)
void softmin_kernel(const float* __restrict__ x, const float* __restrict__ S,
                    float* __restrict__ out, int W, float invW)
{
    __shared__ float ssf[SEGC * 2 * SSTR];   // -S rows, u64 stride SSTR
    __shared__ float sred[NW];

    const int t = threadIdx.x;
    for (int i = t; i < SEGC * 2 * SSTR; i += TPB) {
        int seg = i / (2 * SSTR), off = i - seg * (2 * SSTR);
        ssf[i] = (off < 100) ? -S[seg * 100 + off] : 0.0f;
    }
    __syncthreads();
    const u64* ss2 = reinterpret_cast<const u64*>(ssf);   // [seg*SSTR + idx]

    const int lane = t & 31, warp = t >> 5;
    const int h    = lane >> 4;        // which window of each pair
    const int sub  = lane & 15;        // lane within half
    const int gq   = blockIdx.x * NW + warp;
    const int TQ   = gridDim.x * NW;
    const int NQ   = (W + 3) >> 2;     // quads of windows

    const bool p8 = (lane & 8) != 0;
    const bool p4 = (lane & 4) != 0;
    const bool p2 = (lane & 2) != 0;
    const bool p1 = (lane & 1) != 0;

    // remainder-packing lane constants
    // cells: m(c) = (c+1)/3, j(c) = c - 2*m(c)
    const int c1 = sub >> 1;                 // group1 cell 0..7
    const int m1 = (c1 + 1) / 3;
    const int j1 = c1 - 2 * m1;
    const bool ok2 = (sub < 10);
    const int c2 = ok2 ? (8 + (sub >> 1)) : 8;   // group2 cell 8..12 (clamped)
    const int m2 = (c2 + 1) / 3;
    const int j2 = c2 - 2 * m2;
    const int er = 48 + (sub & 1);           // remainder f2 index
    const int n_own = SRCLANE16(sub);        // stream owned by this lane
    const int src1 = 2 * (n_own & 7);
    const int src2 = 2 * ((n_own - 8) & 7);

    float xsum = 0.0f;

    for (int q = gq; q < NQ; q += TQ) {
        const int wA = 4 * q + h;          // task A windows
        const int wB = 4 * q + 2 + h;      // task B windows
        const int wcA = (wA < W) ? wA : (W - 1);
        const int wcB = (wB < W) ? wB : (W - 1);
        const u64* xwA = reinterpret_cast<const u64*>(x) + (size_t)wcA * 125u;
        const u64* xwB = reinterpret_cast<const u64*>(x) + (size_t)wcB * 125u;

        u64 accA[13], accB[13];
#pragma unroll
        for (int c = 0; c < 13; ++c) { accA[c] = 0ull; accB[c] = 0ull; }

        // ---- main loop: 3 FULL slices (idx 0..47), no predication ----
        // cell ids: (m,m)=3m ; (m,m-1)=3m-1 ; (m-1,m)=3m-2
        u64 xpA[3], xpB[3];
#pragma unroll
        for (int m = 0; m < SEGC; ++m) {
            u64 xvA[3], xvB[3];
#pragma unroll
            for (int k = 0; k < 3; ++k) {
                const int idx = sub + 16 * k;          // <= 47, unconditional
                xvA[k] = xwA[m * 50 + idx];
                xvB[k] = xwB[m * 50 + idx];
            }
            // sv = -s[m] shared by A and B, cells (m,m) and (m-1,m)
#pragma unroll
            for (int k = 0; k < 3; ++k) {
                const int idx = sub + 16 * k;
                u64 sv = ss2[m * SSTR + idx];
                { u64 d = f2_add(xvA[k], sv); accA[3 * m] = f2_fma(d, d, accA[3 * m]); }
                { u64 d = f2_add(xvB[k], sv); accB[3 * m] = f2_fma(d, d, accB[3 * m]); }
                if (m > 0) {
                    { u64 d = f2_add(xpA[k], sv); accA[3 * m - 2] = f2_fma(d, d, accA[3 * m - 2]); }
                    { u64 d = f2_add(xpB[k], sv); accB[3 * m - 2] = f2_fma(d, d, accB[3 * m - 2]); }
                }
            }
            // svp = -s[m-1] shared by A and B, cell (m,m-1)
            if (m > 0) {
#pragma unroll
                for (int k = 0; k < 3; ++k) {
                    const int idx = sub + 16 * k;
                    u64 svp = ss2[(m - 1) * SSTR + idx];
                    { u64 d = f2_add(xvA[k], svp); accA[3 * m - 1] = f2_fma(d, d, accA[3 * m - 1]); }
                    { u64 d = f2_add(xvB[k], svp); accB[3 * m - 1] = f2_fma(d, d, accB[3 * m - 1]); }
                }
            }
#pragma unroll
            for (int k = 0; k < 3; ++k) { xpA[k] = xvA[k]; xpB[k] = xvB[k]; }
        }

        // ---- packed remainder: f2 idx 48,49 of all 13 cells ----
        // group1: lane sub -> cell sub/2 (cells 0..7); group2: cells 8..12.
        u64 sr1 = ss2[j1 * SSTR + er];
        u64 sr2 = ok2 ? ss2[j2 * SSTR + er] : 0ull;

        u64 xrA1 = xwA[m1 * 50 + er];
        u64 xrB1 = xwB[m1 * 50 + er];
        u64 xrA2 = ok2 ? xwA[m2 * 50 + er] : 0ull;
        u64 xrB2 = ok2 ? xwB[m2 * 50 + er] : 0ull;

        u64 dA1 = f2_add(xrA1, sr1);  float fA1 = f2_hadd(f2_fma(dA1, dA1, 0ull));
        u64 dB1 = f2_add(xrB1, sr1);  float fB1 = f2_hadd(f2_fma(dB1, dB1, 0ull));
        u64 dA2 = f2_add(xrA2, sr2);  float fA2 = f2_hadd(f2_fma(dA2, dA2, 0ull));
        u64 dB2 = f2_add(xrB2, sr2);  float fB2 = f2_hadd(f2_fma(dB2, dB2, 0ull));
        fA1 += __shfl_xor_sync(0xffffffffu, fA1, 1);
        fB1 += __shfl_xor_sync(0xffffffffu, fB1, 1);
        fA2 += __shfl_xor_sync(0xffffffffu, fA2, 1);
        fB2 += __shfl_xor_sync(0xffffffffu, fB2, 1);

        // Two independent tails — ptxas interleaves their shfl chains.
        float dA = band_tail(accA, p8, p4, p2, p1, fA1, fA2, n_own, src1, src2);
        float dB = band_tail(accB, p8, p4, p2, p1, fB1, fB2, n_own, src1, src2);

        float xiA = __expf(-0.01f * sqrtf(dA));
        float xiB = __expf(-0.01f * sqrtf(dB));
        if (wA < W) xsum += xiA;
        if (wB < W) xsum += xiB;
    }

    // epilogue: lane 0 of each half carries its half's sum
    float v = (sub == 0) ? xsum : 0.0f;
    v += __shfl_xor_sync(0xffffffffu, v, 16);
    v += __shfl_xor_sync(0xffffffffu, v, 8);
    v += __shfl_xor_sync(0xffffffffu, v, 4);
    v += __shfl_xor_sync(0xffffffffu, v, 2);
    v += __shfl_xor_sync(0xffffffffu, v, 1);
    if ((t & 31) == 0) sred[warp] = v;
    __syncthreads();
    if (t == 0) {
        float s = 0.0f;
#pragma unroll
        for (int i = 0; i < NW; ++i) s += sred[i];
        atomicAdd(out, s * invW);
    }
}

extern "C" void kernel_launch(void* const* d_in, const int* in_sizes, int n_in,
                              void* d_out, int out_size)
{
    const float* x = (const float*)d_in[0];
    const float* S = (const float*)d_in[1];
    float* out = (float*)d_out;

    const int Q    = in_sizes[0];
    const int L    = in_sizes[1];       // 500
    const int step = L / 2;             // 250
    const int W    = (Q - L + step - 1) / step;   // 79998
    const float invW = 1.0f / (float)W;

    zero_kernel<<<1, 1>>>(out);
    softmin_kernel<<<BLOCKS, TPB>>>(x, S, out, W, invW);
}